// round 13
// baseline (speedup 1.0000x reference)
#include <cuda_runtime.h>
#include <cuda_bf16.h>
#include <cstdint>
#include <cstddef>

// Problem constants
#define Bdim 2
#define Tdim 4096
#define Cdim 1024
#define Hdim 16
#define Ddim 64
#define MROWS (Bdim*Tdim)   // 8192
#define PLANE (MROWS*Cdim)
#define WPLANE (Cdim*Cdim)

#define LOG2E 1.4426950408889634f
#define LN2F  0.69314718055994531f

// ====================== helpers ============================================
__device__ __forceinline__ uint32_t smem_to_u32(const void* p) {
    uint32_t addr;
    asm("{ .reg .u64 tmp; cvta.to.shared.u64 tmp, %1; cvt.u32.u64 %0, tmp; }"
        : "=r"(addr) : "l"(p));
    return addr;
}
#define SWZ(x) ((x) ^ (((x) >> 3) & 0x70))

__device__ __forceinline__ void cpa16(uint32_t s, const void* g) {
    asm volatile("cp.async.cg.shared.global [%0], [%1], 16;" :: "r"(s), "l"(g));
}
#define CPA_COMMIT() asm volatile("cp.async.commit_group;")
#define CPA_WAIT0()  asm volatile("cp.async.wait_group 0;")
#define CPA_WAIT1()  asm volatile("cp.async.wait_group 1;")

__device__ __forceinline__ void ldm_x4(uint32_t* r, uint32_t addr) {
    asm volatile("ldmatrix.sync.aligned.m8n8.x4.shared.b16 {%0,%1,%2,%3}, [%4];"
        : "=r"(r[0]), "=r"(r[1]), "=r"(r[2]), "=r"(r[3]) : "r"(addr));
}
__device__ __forceinline__ void ldm_x4t(uint32_t* r, uint32_t addr) {
    asm volatile("ldmatrix.sync.aligned.m8n8.x4.trans.shared.b16 {%0,%1,%2,%3}, [%4];"
        : "=r"(r[0]), "=r"(r[1]), "=r"(r[2]), "=r"(r[3]) : "r"(addr));
}
__device__ __forceinline__ void mma16816(float* d, const uint32_t* a, const uint32_t* b) {
    asm volatile(
        "mma.sync.aligned.m16n8k16.row.col.f32.bf16.bf16.f32 "
        "{%0,%1,%2,%3}, {%4,%5,%6,%7}, {%8,%9}, {%0,%1,%2,%3};"
        : "+f"(d[0]), "+f"(d[1]), "+f"(d[2]), "+f"(d[3])
        : "r"(a[0]), "r"(a[1]), "r"(a[2]), "r"(a[3]), "r"(b[0]), "r"(b[1]));
}
__device__ __forceinline__ float ex2f(float x) {
    float y; asm("ex2.approx.ftz.f32 %0, %1;" : "=f"(y) : "f"(x)); return y;
}

// ====================== scratch (static device globals) ====================
__device__ __nv_bfloat16 g_xhi[PLANE];
__device__ __nv_bfloat16 g_xlo[PLANE];
__device__ __nv_bfloat16 g_cwsh[Cdim * 3 * Cdim];   // c_attn_w split (no transpose)
__device__ __nv_bfloat16 g_cwsl[Cdim * 3 * Cdim];
__device__ __nv_bfloat16 g_wTh[4 * WPLANE];         // q_w^T, k_w^T, v_w^T, o_w^T
__device__ __nv_bfloat16 g_wTl[4 * WPLANE];
__device__ __nv_bfloat16 g_weffh[3 * WPLANE];       // W_eff^T planes for q,k,v
__device__ __nv_bfloat16 g_weffl[3 * WPLANE];
__device__ float g_beff[3 * Cdim];
__device__ float g_zero[Cdim];                      // zero-initialized
__device__ __nv_bfloat16 g_attnh[3 * PLANE];        // q,k,v hi planes
__device__ __nv_bfloat16 g_attnl[3 * PLANE];
__device__ __nv_bfloat16 g_yh[PLANE];
__device__ __nv_bfloat16 g_yl[PLANE];
__device__ float g_o1[PLANE];
__device__ float g_o2[PLANE];
__device__ float g_o3[PLANE];
__device__ float g_l1[MROWS * Hdim];
__device__ float g_l2[MROWS * Hdim];
__device__ float g_l3[MROWS * Hdim];

// ====================== conversion kernels =================================
__global__ __launch_bounds__(256) void split2_kernel(
    const float* __restrict__ x, __nv_bfloat16* __restrict__ xh, __nv_bfloat16* __restrict__ xl,
    const float* __restrict__ w, __nv_bfloat16* __restrict__ wh, __nv_bfloat16* __restrict__ wl)
{
    const int XB = PLANE / 1024;
    int bid = blockIdx.x;
    const float* in; __nv_bfloat16 *hi, *lo;
    if (bid < XB) { in = x; hi = xh; lo = xl; }
    else { bid -= XB; in = w; hi = wh; lo = wl; }
    int i = (bid * 256 + threadIdx.x) * 4;
    float4 v = *(const float4*)(in + i);
    float vv[4] = {v.x, v.y, v.z, v.w};
    __nv_bfloat16 h[4], l[4];
#pragma unroll
    for (int k = 0; k < 4; k++) {
        h[k] = __float2bfloat16(vv[k]);
        l[k] = __float2bfloat16(vv[k] - __bfloat162float(h[k]));
    }
    *(uint2*)(hi + i) = *(uint2*)h;
    *(uint2*)(lo + i) = *(uint2*)l;
}

__global__ __launch_bounds__(256) void transpose_split4(
    const float* __restrict__ w0, const float* __restrict__ w1,
    const float* __restrict__ w2, const float* __restrict__ w3,
    __nv_bfloat16* __restrict__ Th, __nv_bfloat16* __restrict__ Tl)
{
    __shared__ float tile[32][33];
    const int z = blockIdx.z;
    const float* W = (z == 0) ? w0 : (z == 1) ? w1 : (z == 2) ? w2 : w3;
    __nv_bfloat16* th = Th + (size_t)z * WPLANE;
    __nv_bfloat16* tl = Tl + (size_t)z * WPLANE;
    int n0 = blockIdx.x * 32, k0 = blockIdx.y * 32;
    int tx = threadIdx.x & 31, ty = threadIdx.x >> 5;
#pragma unroll
    for (int r = 0; r < 4; r++)
        tile[ty + r * 8][tx] = W[(size_t)(k0 + ty + r * 8) * Cdim + n0 + tx];
    __syncthreads();
#pragma unroll
    for (int r = 0; r < 4; r++) {
        float v = tile[tx][ty + r * 8];
        __nv_bfloat16 h = __float2bfloat16(v);
        size_t o = (size_t)(n0 + ty + r * 8) * Cdim + k0 + tx;
        th[o] = h;
        tl[o] = __float2bfloat16(v - __bfloat162float(h));
    }
}

__global__ __launch_bounds__(256) void beff_kernel(
    const float* __restrict__ cab,
    const float* __restrict__ w0, const float* __restrict__ w1, const float* __restrict__ w2,
    const float* __restrict__ b0, const float* __restrict__ b1, const float* __restrict__ b2,
    float* __restrict__ beff)
{
    int i = blockIdx.x * 256 + threadIdx.x;
    int z = blockIdx.y;
    const float* W  = (z == 0) ? w0 : (z == 1) ? w1 : w2;
    const float* bb = (z == 0) ? b0 : (z == 1) ? b1 : b2;
    const float* c = cab + z * Cdim;
    float acc = bb[i];
    for (int k = 0; k < Cdim; k++) acc += c[k] * W[(size_t)k * Cdim + i];
    beff[z * Cdim + i] = acc;
}

// ====================== HMMA bf16x3 GEMM (batched over z) ==================
// C = alpha_z * (A @ B^T + bias); 3-stage cp.async pipeline, 1 sync/chunk.
// MMA terms issued in 3 passes over all 16 accumulators (RAW-chain spacing).
#define HG_STAGE 65536
#define HG_SMEM  (3 * HG_STAGE)

__device__ __forceinline__ void hg_load_stage(
    uint32_t sbase, int buf,
    const __nv_bfloat16* __restrict__ a_hi, const __nv_bfloat16* __restrict__ a_lo,
    size_t m0, int lda,
    const __nv_bfloat16* __restrict__ b_hi, const __nv_bfloat16* __restrict__ b_lo,
    size_t n0, int ldb, int k0, int tid)
{
    uint32_t sAh = sbase + buf * HG_STAGE;
    uint32_t sAl = sAh + 16384;
    uint32_t sBh = sAh + 32768;
    uint32_t sBl = sAh + 49152;
#pragma unroll
    for (int t = 0; t < 4; t++) {
        int i = tid + t * 256;
        int row = i >> 3, u = i & 7;
        uint32_t soff = SWZ(row * 128 + u * 16);
        size_t ga = (m0 + row) * (size_t)lda + k0 + u * 8;
        size_t gb = (n0 + row) * (size_t)ldb + k0 + u * 8;
        cpa16(sAh + soff, a_hi + ga);
        cpa16(sAl + soff, a_lo + ga);
        cpa16(sBh + soff, b_hi + gb);
        cpa16(sBl + soff, b_lo + gb);
    }
}

__global__ __launch_bounds__(256, 1) void hmma_gemm(
    const __nv_bfloat16* __restrict__ a_hi, const __nv_bfloat16* __restrict__ a_lo, int lda,
    const __nv_bfloat16* __restrict__ b_hi, const __nv_bfloat16* __restrict__ b_lo, int ldb,
    const float* __restrict__ bias,
    float* __restrict__ outf,
    __nv_bfloat16* __restrict__ out_hi, __nv_bfloat16* __restrict__ out_lo,
    int ldc, int K, float alpha, float alpha2, int mode,
    int az, int bz, int biasz, int cz)
{
    const int z = blockIdx.z;
    a_hi += (size_t)z * az;  a_lo += (size_t)z * az;
    b_hi += (size_t)z * bz;  b_lo += (size_t)z * bz;
    bias += (size_t)z * biasz;
    if (outf)  outf  += (size_t)z * cz;
    if (out_hi) { out_hi += (size_t)z * cz; out_lo += (size_t)z * cz; }
    const float alf = (z == 0) ? alpha : alpha2;

    extern __shared__ char sm[];
    const uint32_t sbase = smem_to_u32(sm);
    const int tid  = threadIdx.x;
    const int warp = tid >> 5, lane = tid & 31;
    const int wm0 = (warp >> 2) * 64;
    const int wn0 = (warp & 3) * 32;
    const size_t m0 = (size_t)blockIdx.y * 128;
    const size_t n0 = (size_t)blockIdx.x * 128;
    const int NC = K >> 6;

    float acc[4][4][4];
#pragma unroll
    for (int i = 0; i < 4; i++)
#pragma unroll
        for (int j = 0; j < 4; j++)
#pragma unroll
            for (int r = 0; r < 4; r++) acc[i][j][r] = 0.f;

    hg_load_stage(sbase, 0, a_hi, a_lo, m0, lda, b_hi, b_lo, n0, ldb, 0, tid);
    CPA_COMMIT();
    hg_load_stage(sbase, 1, a_hi, a_lo, m0, lda, b_hi, b_lo, n0, ldb, 64, tid);
    CPA_COMMIT();

    const int g = lane >> 3;
    const int l7 = lane & 7;

    for (int c = 0; c < NC; ++c) {
        if (c + 1 < NC) { CPA_WAIT1(); } else { CPA_WAIT0(); }
        __syncthreads();
        if (c + 2 < NC) {
            hg_load_stage(sbase, (c + 2) % 3, a_hi, a_lo, m0, lda,
                          b_hi, b_lo, n0, ldb, (c + 2) * 64, tid);
            CPA_COMMIT();
        }
        uint32_t sAh = sbase + (c % 3) * HG_STAGE;
        uint32_t sAl = sAh + 16384;
        uint32_t sBh = sAh + 32768;
        uint32_t sBl = sAh + 49152;

#pragma unroll
        for (int ks = 0; ks < 4; ks++) {
            uint32_t ah[4][4], al[4][4];
            {
                int arow = wm0 + (g & 1) * 8 + l7;
                int akb  = ks * 32 + ((g >> 1) & 1) * 16;
#pragma unroll
                for (int mt = 0; mt < 4; mt++) {
                    uint32_t off = SWZ((arow + mt * 16) * 128 + akb);
                    ldm_x4(ah[mt], sAh + off);
                    ldm_x4(al[mt], sAl + off);
                }
            }
            uint32_t bh[4][2], bl[4][2];
            {
                int nrow = wn0 + ((g >> 1) & 1) * 8 + l7;
                int bkb  = ks * 32 + (g & 1) * 16;
#pragma unroll
                for (int nt = 0; nt < 2; nt++) {
                    uint32_t off = SWZ((nrow + nt * 16) * 128 + bkb);
                    uint32_t r[4];
                    ldm_x4(r, sBh + off);
                    bh[nt * 2 + 0][0] = r[0]; bh[nt * 2 + 0][1] = r[1];
                    bh[nt * 2 + 1][0] = r[2]; bh[nt * 2 + 1][1] = r[3];
                    ldm_x4(r, sBl + off);
                    bl[nt * 2 + 0][0] = r[0]; bl[nt * 2 + 0][1] = r[1];
                    bl[nt * 2 + 1][0] = r[2]; bl[nt * 2 + 1][1] = r[3];
                }
            }
            // 3 passes over all 16 accumulators: RAW chain spacing = 16 MMAs
#pragma unroll
            for (int mt = 0; mt < 4; mt++)
#pragma unroll
                for (int j = 0; j < 4; j++)
                    mma16816(acc[mt][j], ah[mt], bh[j]);
#pragma unroll
            for (int mt = 0; mt < 4; mt++)
#pragma unroll
                for (int j = 0; j < 4; j++)
                    mma16816(acc[mt][j], ah[mt], bl[j]);
#pragma unroll
            for (int mt = 0; mt < 4; mt++)
#pragma unroll
                for (int j = 0; j < 4; j++)
                    mma16816(acc[mt][j], al[mt], bh[j]);
        }
    }

    const int qrow = lane >> 2;
    const int qcol = (lane & 3) * 2;
#pragma unroll
    for (int j = 0; j < 4; j++) {
        size_t col = n0 + wn0 + j * 8 + qcol;
        float b0 = bias[col], b1 = bias[col + 1];
#pragma unroll
        for (int mt = 0; mt < 4; mt++) {
            size_t row0 = m0 + wm0 + mt * 16 + qrow;
            size_t row1 = row0 + 8;
            float v00 = alf * (acc[mt][j][0] + b0);
            float v01 = alf * (acc[mt][j][1] + b1);
            float v10 = alf * (acc[mt][j][2] + b0);
            float v11 = alf * (acc[mt][j][3] + b1);
            if (mode == 0) {
                float2 r0 = {v00, v01}, r1 = {v10, v11};
                *(float2*)(outf + row0 * ldc + col) = r0;
                *(float2*)(outf + row1 * ldc + col) = r1;
            } else {
                __nv_bfloat162 hh0, ll0, hh1, ll1;
                hh0.x = __float2bfloat16(v00); hh0.y = __float2bfloat16(v01);
                ll0.x = __float2bfloat16(v00 - __bfloat162float(hh0.x));
                ll0.y = __float2bfloat16(v01 - __bfloat162float(hh0.y));
                hh1.x = __float2bfloat16(v10); hh1.y = __float2bfloat16(v11);
                ll1.x = __float2bfloat16(v10 - __bfloat162float(hh1.x));
                ll1.y = __float2bfloat16(v11 - __bfloat162float(hh1.y));
                *(uint32_t*)((char*)out_hi + (row0 * ldc + col) * 2) = *(uint32_t*)&hh0;
                *(uint32_t*)((char*)out_lo + (row0 * ldc + col) * 2) = *(uint32_t*)&ll0;
                *(uint32_t*)((char*)out_hi + (row1 * ldc + col) * 2) = *(uint32_t*)&hh1;
                *(uint32_t*)((char*)out_lo + (row1 * ldc + col) * 2) = *(uint32_t*)&ll1;
            }
        }
    }
}

// ================= HMMA dilated attention (all 3 branches, one launch) =====
#define FA_SMEM 98304

__global__ __launch_bounds__(256) void attn_hmma_all(
    const __nv_bfloat16* __restrict__ qh_g, const __nv_bfloat16* __restrict__ ql_g,
    const __nv_bfloat16* __restrict__ kh_g, const __nv_bfloat16* __restrict__ kl_g,
    const __nv_bfloat16* __restrict__ vh_g, const __nv_bfloat16* __restrict__ vl_g,
    float* __restrict__ O1, float* __restrict__ O2, float* __restrict__ O3,
    float* __restrict__ L1, float* __restrict__ L2, float* __restrict__ L3)
{
    extern __shared__ char sm[];
    const uint32_t sbase = smem_to_u32(sm);
    const uint32_t sQh = sbase, sQl = sbase + 16384;

    int bx = blockIdx.x;
    int W, R;
    float *Obuf, *Lbuf;
    if (bx < 32)      { W = 512;  R = 1; Obuf = O1; Lbuf = L1; }
    else if (bx < 48) { W = 1024; R = 2; Obuf = O2; Lbuf = L2; bx -= 32; }
    else              { W = 2048; R = 4; Obuf = O3; Lbuf = L3; bx -= 48; }
    const int seg = bx >> 2;
    const int qt  = bx & 3;

    const int b   = blockIdx.z;
    const int h   = blockIdx.y;
    const int tid = threadIdx.x;
    const int warp = tid >> 5, lane = tid & 31;
    const int g = lane >> 3, l7 = lane & 7;
    const int segbase = seg * W + (h & (R - 1));
    const int qBase = qt * 128;
    const size_t hoff = (size_t)h * Ddim;

#pragma unroll
    for (int t = 0; t < 4; t++) {
        int i = tid + t * 256;
        int row = i >> 3, u = i & 7;
        int tp = segbase + (qBase + row) * R;
        size_t gidx = (size_t)(b * Tdim + tp) * Cdim + hoff + u * 8;
        uint32_t off = SWZ(row * 128 + u * 16);
        cpa16(sQh + off, qh_g + gidx);
        cpa16(sQl + off, ql_g + gidx);
    }
    {
        uint32_t st = sbase + 32768;
#pragma unroll
        for (int t = 0; t < 2; t++) {
            int i = tid + t * 256;
            int row = i >> 3, u = i & 7;
            int tp = segbase + row * R;
            size_t gidx = (size_t)(b * Tdim + tp) * Cdim + hoff + u * 8;
            uint32_t off = SWZ(row * 128 + u * 16);
            cpa16(st +         off, kh_g + gidx);
            cpa16(st +  8192 + off, kl_g + gidx);
            cpa16(st + 16384 + off, vh_g + gidx);
            cpa16(st + 24576 + off, vl_g + gidx);
        }
    }
    CPA_COMMIT();

    uint32_t qfh[4][4], qfl[4][4];
    float oa[8][4];
#pragma unroll
    for (int nt = 0; nt < 8; nt++)
#pragma unroll
        for (int r = 0; r < 4; r++) oa[nt][r] = 0.f;
    float m0 = -1e30f, m1 = -1e30f, l0 = 0.f, l1 = 0.f;

    const int r0 = lane >> 2;
    const int row0 = qBase + warp * 16 + r0;
    const int row1 = row0 + 8;
    const int colb = (lane & 3) * 2;

    const int ntiles = qt * 2 + 2;
    for (int jt = 0; jt < ntiles; jt++) {
        const int j0 = jt * 64;
        CPA_WAIT0();
        __syncthreads();
        if (jt == 0) {
            int arow = warp * 16 + (g & 1) * 8 + l7;
#pragma unroll
            for (int ks = 0; ks < 4; ks++) {
                int akb = ks * 32 + ((g >> 1) & 1) * 16;
                uint32_t off = SWZ(arow * 128 + akb);
                ldm_x4(qfh[ks], sQh + off);
                ldm_x4(qfl[ks], sQl + off);
            }
        }
        if (jt + 1 < ntiles) {
            uint32_t st = sbase + 32768 + ((jt + 1) & 1) * 32768;
            int jn0 = (jt + 1) * 64;
#pragma unroll
            for (int t = 0; t < 2; t++) {
                int i = tid + t * 256;
                int row = i >> 3, u = i & 7;
                int tp = segbase + (jn0 + row) * R;
                size_t gidx = (size_t)(b * Tdim + tp) * Cdim + hoff + u * 8;
                uint32_t off = SWZ(row * 128 + u * 16);
                cpa16(st +         off, kh_g + gidx);
                cpa16(st +  8192 + off, kl_g + gidx);
                cpa16(st + 16384 + off, vh_g + gidx);
                cpa16(st + 24576 + off, vl_g + gidx);
            }
            CPA_COMMIT();
        }

        uint32_t sKh = sbase + 32768 + (jt & 1) * 32768;
        uint32_t sKl = sKh + 8192;
        uint32_t sVh = sKh + 16384;
        uint32_t sVl = sKh + 24576;

        float sa[8][4];
#pragma unroll
        for (int j = 0; j < 8; j++)
#pragma unroll
            for (int r = 0; r < 4; r++) sa[j][r] = 0.f;

#pragma unroll
        for (int ks = 0; ks < 4; ks++) {
            uint32_t kfh[8][2], kfl[8][2];
            int nrow = ((g >> 1) & 1) * 8 + l7;
            int bkb  = ks * 32 + (g & 1) * 16;
#pragma unroll
            for (int nt16 = 0; nt16 < 4; nt16++) {
                uint32_t off = SWZ((nrow + nt16 * 16) * 128 + bkb);
                uint32_t r[4];
                ldm_x4(r, sKh + off);
                kfh[nt16 * 2 + 0][0] = r[0]; kfh[nt16 * 2 + 0][1] = r[1];
                kfh[nt16 * 2 + 1][0] = r[2]; kfh[nt16 * 2 + 1][1] = r[3];
                ldm_x4(r, sKl + off);
                kfl[nt16 * 2 + 0][0] = r[0]; kfl[nt16 * 2 + 0][1] = r[1];
                kfl[nt16 * 2 + 1][0] = r[2]; kfl[nt16 * 2 + 1][1] = r[3];
            }
            // 3 passes over all 8 accumulators
#pragma unroll
            for (int j = 0; j < 8; j++) mma16816(sa[j], qfh[ks], kfh[j]);
#pragma unroll
            for (int j = 0; j < 8; j++) mma16816(sa[j], qfh[ks], kfl[j]);
#pragma unroll
            for (int j = 0; j < 8; j++) mma16816(sa[j], qfl[ks], kfh[j]);
        }

        if (jt >= 2 * qt) {
#pragma unroll
            for (int j = 0; j < 8; j++) {
                int key = j0 + j * 8 + colb;
                if (key     > row0) sa[j][0] = -1e30f;
                if (key + 1 > row0) sa[j][1] = -1e30f;
                if (key     > row1) sa[j][2] = -1e30f;
                if (key + 1 > row1) sa[j][3] = -1e30f;
            }
        }

        float rm0 = sa[0][0], rm1 = sa[0][2];
#pragma unroll
        for (int j = 0; j < 8; j++) {
            rm0 = fmaxf(rm0, fmaxf(sa[j][0], sa[j][1]));
            rm1 = fmaxf(rm1, fmaxf(sa[j][2], sa[j][3]));
        }
        rm0 = fmaxf(rm0, __shfl_xor_sync(0xffffffffu, rm0, 1));
        rm0 = fmaxf(rm0, __shfl_xor_sync(0xffffffffu, rm0, 2));
        rm1 = fmaxf(rm1, __shfl_xor_sync(0xffffffffu, rm1, 1));
        rm1 = fmaxf(rm1, __shfl_xor_sync(0xffffffffu, rm1, 2));
        float mn0 = fmaxf(m0, rm0), mn1 = fmaxf(m1, rm1);
        float sc0 = ex2f(m0 - mn0), sc1 = ex2f(m1 - mn1);
        float rs0 = 0.f, rs1 = 0.f;
#pragma unroll
        for (int j = 0; j < 8; j++) {
            sa[j][0] = ex2f(sa[j][0] - mn0);
            sa[j][1] = ex2f(sa[j][1] - mn0);
            sa[j][2] = ex2f(sa[j][2] - mn1);
            sa[j][3] = ex2f(sa[j][3] - mn1);
            rs0 += sa[j][0] + sa[j][1];
            rs1 += sa[j][2] + sa[j][3];
        }
        rs0 += __shfl_xor_sync(0xffffffffu, rs0, 1);
        rs0 += __shfl_xor_sync(0xffffffffu, rs0, 2);
        rs1 += __shfl_xor_sync(0xffffffffu, rs1, 1);
        rs1 += __shfl_xor_sync(0xffffffffu, rs1, 2);
        l0 = l0 * sc0 + rs0; l1 = l1 * sc1 + rs1;
        m0 = mn0; m1 = mn1;
#pragma unroll
        for (int nt = 0; nt < 8; nt++) {
            oa[nt][0] *= sc0; oa[nt][1] *= sc0;
            oa[nt][2] *= sc1; oa[nt][3] *= sc1;
        }

        // P fragments for all 4 k-chunks first, then 3 MMA passes per chunk
#pragma unroll
        for (int kc = 0; kc < 4; kc++) {
            uint32_t ah[4], al[4];
#pragma unroll
            for (int half = 0; half < 2; half++) {
                const float* p0 = sa[kc * 2 + half];
                __nv_bfloat162 h01, h23, lo01, lo23;
                h01.x = __float2bfloat16(p0[0]); h01.y = __float2bfloat16(p0[1]);
                h23.x = __float2bfloat16(p0[2]); h23.y = __float2bfloat16(p0[3]);
                lo01.x = __float2bfloat16(p0[0] - __bfloat162float(h01.x));
                lo01.y = __float2bfloat16(p0[1] - __bfloat162float(h01.y));
                lo23.x = __float2bfloat16(p0[2] - __bfloat162float(h23.x));
                lo23.y = __float2bfloat16(p0[3] - __bfloat162float(h23.y));
                ah[half * 2 + 0] = *(uint32_t*)&h01;
                ah[half * 2 + 1] = *(uint32_t*)&h23;
                al[half * 2 + 0] = *(uint32_t*)&lo01;
                al[half * 2 + 1] = *(uint32_t*)&lo23;
            }

            uint32_t vfh[8][2], vfl[8][2];
            int vrow = kc * 16 + (g & 1) * 8 + l7;
            int nhalf = (g >> 1) & 1;
#pragma unroll
            for (int nt16 = 0; nt16 < 4; nt16++) {
                uint32_t off = SWZ(vrow * 128 + nt16 * 32 + nhalf * 16);
                uint32_t r[4];
                ldm_x4t(r, sVh + off);
                vfh[nt16 * 2 + 0][0] = r[0]; vfh[nt16 * 2 + 0][1] = r[1];
                vfh[nt16 * 2 + 1][0] = r[2]; vfh[nt16 * 2 + 1][1] = r[3];
                ldm_x4t(r, sVl + off);
                vfl[nt16 * 2 + 0][0] = r[0]; vfl[nt16 * 2 + 0][1] = r[1];
                vfl[nt16 * 2 + 1][0] = r[2]; vfl[nt16 * 2 + 1][1] = r[3];
            }
            // 3 passes over all 8 accumulators
#pragma unroll
            for (int nt = 0; nt < 8; nt++) mma16816(oa[nt], ah, vfh[nt]);
#pragma unroll
            for (int nt = 0; nt < 8; nt++) mma16816(oa[nt], al, vfh[nt]);
#pragma unroll
            for (int nt = 0; nt < 8; nt++) mma16816(oa[nt], ah, vfl[nt]);
        }
        __syncthreads();
    }

    float inv0 = 1.f / l0, inv1 = 1.f / l1;
    int tp0 = segbase + row0 * R;
    int tp1 = segbase + row1 * R;
    size_t ob0 = (size_t)(b * Tdim + tp0) * Cdim + hoff;
    size_t ob1 = (size_t)(b * Tdim + tp1) * Cdim + hoff;
#pragma unroll
    for (int nt = 0; nt < 8; nt++) {
        int d = nt * 8 + colb;
        float2 w0 = {oa[nt][0] * inv0, oa[nt][1] * inv0};
        float2 w1 = {oa[nt][2] * inv1, oa[nt][3] * inv1};
        *(float2*)(Obuf + ob0 + d) = w0;
        *(float2*)(Obuf + ob1 + d) = w1;
    }
    if ((lane & 3) == 0) {
        Lbuf[(size_t)(b * Tdim + tp0) * Hdim + h] = m0 * LN2F + logf(l0);
        Lbuf[(size_t)(b * Tdim + tp1) * Hdim + h] = m1 * LN2F + logf(l1);
    }
}

// ---------------- combine branches -> y (bf16 hi/lo split out) -------------
__global__ __launch_bounds__(256) void combine_kernel(
    const float* __restrict__ O1, const float* __restrict__ O2,
    const float* __restrict__ O3, const float* __restrict__ L1,
    const float* __restrict__ L2, const float* __restrict__ L3,
    __nv_bfloat16* __restrict__ Yh, __nv_bfloat16* __restrict__ Yl)
{
    int idx = blockIdx.x * 256 + threadIdx.x;
    int c = idx & (Cdim - 1);
    int bt = idx >> 10;
    int t = bt & (Tdim - 1);
    int h = c >> 6;
    int li = bt * Hdim + h;

    float l1 = L1[li];
    bool p2 = (((t ^ h) & 1) == 0);
    bool p3 = (((t ^ h) & 3) == 0);
    float l2 = p2 ? L2[li] : -1e30f;
    float l3 = p3 ? L3[li] : -1e30f;
    float m = fmaxf(l1, fmaxf(l2, l3));
    float w1 = __expf(l1 - m);
    float w2 = p2 ? __expf(l2 - m) : 0.f;
    float w3 = p3 ? __expf(l3 - m) : 0.f;
    float num = w1 * O1[idx];
    if (p2) num += w2 * O2[idx];
    if (p3) num += w3 * O3[idx];
    float y = num / (w1 + w2 + w3);
    __nv_bfloat16 hh = __float2bfloat16(y);
    Yh[idx] = hh;
    Yl[idx] = __float2bfloat16(y - __bfloat162float(hh));
}

// ---------------- launcher --------------------------------------------------
extern "C" void kernel_launch(void* const* d_in, const int* in_sizes, int n_in,
                              void* d_out, int out_size)
{
    const float* x        = (const float*)d_in[0];
    const float* c_attn_w = (const float*)d_in[1];
    const float* c_attn_b = (const float*)d_in[2];
    const float* q_w      = (const float*)d_in[3];
    const float* q_b      = (const float*)d_in[4];
    const float* k_w      = (const float*)d_in[5];
    const float* k_b      = (const float*)d_in[6];
    const float* v_w      = (const float*)d_in[7];
    const float* v_b      = (const float*)d_in[8];
    const float* o_w      = (const float*)d_in[9];
    const float* o_b      = (const float*)d_in[10];
    float* out = (float*)d_out;

    __nv_bfloat16 *p_xhi, *p_xlo, *p_cwsh, *p_cwsl, *p_wTh, *p_wTl;
    __nv_bfloat16 *p_weffh, *p_weffl, *p_attnh, *p_attnl, *p_yh, *p_yl;
    float *p_beff, *p_zero, *p_o1, *p_o2, *p_o3, *p_l1, *p_l2, *p_l3;
    cudaGetSymbolAddress((void**)&p_xhi, g_xhi);
    cudaGetSymbolAddress((void**)&p_xlo, g_xlo);
    cudaGetSymbolAddress((void**)&p_cwsh, g_cwsh);
    cudaGetSymbolAddress((void**)&p_cwsl, g_cwsl);
    cudaGetSymbolAddress((void**)&p_wTh, g_wTh);
    cudaGetSymbolAddress((void**)&p_wTl, g_wTl);
    cudaGetSymbolAddress((void**)&p_weffh, g_weffh);
    cudaGetSymbolAddress((void**)&p_weffl, g_weffl);
    cudaGetSymbolAddress((void**)&p_beff, g_beff);
    cudaGetSymbolAddress((void**)&p_zero, g_zero);
    cudaGetSymbolAddress((void**)&p_attnh, g_attnh);
    cudaGetSymbolAddress((void**)&p_attnl, g_attnl);
    cudaGetSymbolAddress((void**)&p_yh, g_yh);
    cudaGetSymbolAddress((void**)&p_yl, g_yl);
    cudaGetSymbolAddress((void**)&p_o1, g_o1);
    cudaGetSymbolAddress((void**)&p_o2, g_o2);
    cudaGetSymbolAddress((void**)&p_o3, g_o3);
    cudaGetSymbolAddress((void**)&p_l1, g_l1);
    cudaGetSymbolAddress((void**)&p_l2, g_l2);
    cudaGetSymbolAddress((void**)&p_l3, g_l3);

    __nv_bfloat16* p_owh = p_wTh + 3 * (size_t)WPLANE;
    __nv_bfloat16* p_owl = p_wTl + 3 * (size_t)WPLANE;

    cudaFuncSetAttribute(attn_hmma_all, cudaFuncAttributeMaxDynamicSharedMemorySize, FA_SMEM);
    cudaFuncSetAttribute(hmma_gemm, cudaFuncAttributeMaxDynamicSharedMemorySize, HG_SMEM);

    // ---- conversions ----
    split2_kernel<<<(PLANE + 3 * WPLANE) / 1024, 256>>>(
        x, p_xhi, p_xlo, c_attn_w, p_cwsh, p_cwsl);
    transpose_split4<<<dim3(32, 32, 4), 256>>>(q_w, k_w, v_w, o_w, p_wTh, p_wTl);
    beff_kernel<<<dim3(Cdim / 256, 3), 256>>>(c_attn_b, q_w, k_w, v_w, q_b, k_b, v_b, p_beff);

    // ---- weight combine: W_eff^T[z] = wT[z] @ cw_slice[z]^T (batched z=3) --
    hmma_gemm<<<dim3(Cdim / 128, Cdim / 128, 3), 256, HG_SMEM>>>(
        p_wTh, p_wTl, Cdim, p_cwsh, p_cwsl, 3 * Cdim, p_zero,
        nullptr, p_weffh, p_weffl, Cdim, Cdim, 1.f, 1.f, 1,
        WPLANE, Cdim, 0, WPLANE);

    // ---- fused q/k/v projections: attn[z] = x @ W_eff[z]^T + b_eff[z] ------
    hmma_gemm<<<dim3(Cdim / 128, MROWS / 128, 3), 256, HG_SMEM>>>(
        p_xhi, p_xlo, Cdim, p_weffh, p_weffl, Cdim, p_beff,
        nullptr, p_attnh, p_attnl, Cdim, Cdim, 0.125f * LOG2E, 1.f, 1,
        0, WPLANE, Cdim, PLANE);

    __nv_bfloat16* p_qh = p_attnh + 0 * (size_t)PLANE; __nv_bfloat16* p_ql = p_attnl + 0 * (size_t)PLANE;
    __nv_bfloat16* p_kh = p_attnh + 1 * (size_t)PLANE; __nv_bfloat16* p_kl = p_attnl + 1 * (size_t)PLANE;
    __nv_bfloat16* p_vh = p_attnh + 2 * (size_t)PLANE; __nv_bfloat16* p_vl = p_attnl + 2 * (size_t)PLANE;

    // ---- all three dilated-attention branches in ONE launch ----
    attn_hmma_all<<<dim3(56, Hdim, Bdim), 256, FA_SMEM>>>(
        p_qh, p_ql, p_kh, p_kl, p_vh, p_vl,
        p_o1, p_o2, p_o3, p_l1, p_l2, p_l3);

    // ---- combine -> y (bf16 split) ----
    combine_kernel<<<PLANE / 256, 256>>>(
        p_o1, p_o2, p_o3, p_l1, p_l2, p_l3, p_yh, p_yl);

    // ---- out = y @ o_w + o_b (fp32) ----
    hmma_gemm<<<dim3(Cdim / 128, MROWS / 128, 1), 256, HG_SMEM>>>(
        p_yh, p_yl, Cdim, p_owh, p_owl, Cdim, o_b,
        out, nullptr, nullptr, Cdim, Cdim, 1.f, 1.f, 0,
        0, 0, 0, 0);
}

// round 14
// speedup vs baseline: 1.0995x; 1.0995x over previous
#include <cuda_runtime.h>
#include <cuda_bf16.h>
#include <cstdint>
#include <cstddef>

// Problem constants
#define Bdim 2
#define Tdim 4096
#define Cdim 1024
#define Hdim 16
#define Ddim 64
#define MROWS (Bdim*Tdim)   // 8192
#define PLANE (MROWS*Cdim)
#define WPLANE (Cdim*Cdim)

#define LOG2E 1.4426950408889634f
#define LN2F  0.69314718055994531f

// ====================== helpers ============================================
__device__ __forceinline__ uint32_t smem_to_u32(const void* p) {
    uint32_t addr;
    asm("{ .reg .u64 tmp; cvta.to.shared.u64 tmp, %1; cvt.u32.u64 %0, tmp; }"
        : "=r"(addr) : "l"(p));
    return addr;
}
#define SWZ(x) ((x) ^ (((x) >> 3) & 0x70))

__device__ __forceinline__ void cpa16(uint32_t s, const void* g) {
    asm volatile("cp.async.cg.shared.global [%0], [%1], 16;" :: "r"(s), "l"(g));
}
#define CPA_COMMIT() asm volatile("cp.async.commit_group;")
#define CPA_WAIT0()  asm volatile("cp.async.wait_group 0;")

__device__ __forceinline__ void ldm_x4(uint32_t* r, uint32_t addr) {
    asm volatile("ldmatrix.sync.aligned.m8n8.x4.shared.b16 {%0,%1,%2,%3}, [%4];"
        : "=r"(r[0]), "=r"(r[1]), "=r"(r[2]), "=r"(r[3]) : "r"(addr));
}
__device__ __forceinline__ void ldm_x4t(uint32_t* r, uint32_t addr) {
    asm volatile("ldmatrix.sync.aligned.m8n8.x4.trans.shared.b16 {%0,%1,%2,%3}, [%4];"
        : "=r"(r[0]), "=r"(r[1]), "=r"(r[2]), "=r"(r[3]) : "r"(addr));
}
__device__ __forceinline__ void mma16816(float* d, const uint32_t* a, const uint32_t* b) {
    asm volatile(
        "mma.sync.aligned.m16n8k16.row.col.f32.bf16.bf16.f32 "
        "{%0,%1,%2,%3}, {%4,%5,%6,%7}, {%8,%9}, {%0,%1,%2,%3};"
        : "+f"(d[0]), "+f"(d[1]), "+f"(d[2]), "+f"(d[3])
        : "r"(a[0]), "r"(a[1]), "r"(a[2]), "r"(a[3]), "r"(b[0]), "r"(b[1]));
}
__device__ __forceinline__ float ex2f(float x) {
    float y; asm("ex2.approx.ftz.f32 %0, %1;" : "=f"(y) : "f"(x)); return y;
}

// ====================== scratch (static device globals) ====================
__device__ __nv_bfloat16 g_xhi[PLANE];
__device__ __nv_bfloat16 g_xlo[PLANE];
__device__ __nv_bfloat16 g_cwsh[Cdim * 3 * Cdim];
__device__ __nv_bfloat16 g_cwsl[Cdim * 3 * Cdim];
__device__ __nv_bfloat16 g_wTh[4 * WPLANE];         // q_w^T,k_w^T,v_w^T,o_w^T
__device__ __nv_bfloat16 g_wTl[4 * WPLANE];
__device__ __nv_bfloat16 g_weffh[3 * WPLANE];
__device__ __nv_bfloat16 g_weffl[3 * WPLANE];
__device__ float g_beff[3 * Cdim];
__device__ float g_zero[Cdim];
__device__ __nv_bfloat16 g_attnh[3 * PLANE];
__device__ __nv_bfloat16 g_attnl[3 * PLANE];
__device__ __nv_bfloat16 g_yh[PLANE];
__device__ __nv_bfloat16 g_yl[PLANE];
__device__ float g_o1[PLANE];
__device__ float g_o2[PLANE];
__device__ float g_o3[PLANE];
__device__ float g_l1[MROWS * Hdim];
__device__ float g_l2[MROWS * Hdim];
__device__ float g_l3[MROWS * Hdim];

// ====================== conversion kernels =================================
__global__ __launch_bounds__(256) void split2_kernel(
    const float* __restrict__ x, __nv_bfloat16* __restrict__ xh, __nv_bfloat16* __restrict__ xl,
    const float* __restrict__ w, __nv_bfloat16* __restrict__ wh, __nv_bfloat16* __restrict__ wl)
{
    const int XB = PLANE / 1024;
    int bid = blockIdx.x;
    const float* in; __nv_bfloat16 *hi, *lo;
    if (bid < XB) { in = x; hi = xh; lo = xl; }
    else { bid -= XB; in = w; hi = wh; lo = wl; }
    int i = (bid * 256 + threadIdx.x) * 4;
    float4 v = *(const float4*)(in + i);
    float vv[4] = {v.x, v.y, v.z, v.w};
    __nv_bfloat16 h[4], l[4];
#pragma unroll
    for (int k = 0; k < 4; k++) {
        h[k] = __float2bfloat16(vv[k]);
        l[k] = __float2bfloat16(vv[k] - __bfloat162float(h[k]));
    }
    *(uint2*)(hi + i) = *(uint2*)h;
    *(uint2*)(lo + i) = *(uint2*)l;
}

__global__ __launch_bounds__(256) void transpose_split4(
    const float* __restrict__ w0, const float* __restrict__ w1,
    const float* __restrict__ w2, const float* __restrict__ w3,
    __nv_bfloat16* __restrict__ Th, __nv_bfloat16* __restrict__ Tl)
{
    __shared__ float tile[32][33];
    const int z = blockIdx.z;
    const float* W = (z == 0) ? w0 : (z == 1) ? w1 : (z == 2) ? w2 : w3;
    __nv_bfloat16* th = Th + (size_t)z * WPLANE;
    __nv_bfloat16* tl = Tl + (size_t)z * WPLANE;
    int n0 = blockIdx.x * 32, k0 = blockIdx.y * 32;
    int tx = threadIdx.x & 31, ty = threadIdx.x >> 5;
#pragma unroll
    for (int r = 0; r < 4; r++)
        tile[ty + r * 8][tx] = W[(size_t)(k0 + ty + r * 8) * Cdim + n0 + tx];
    __syncthreads();
#pragma unroll
    for (int r = 0; r < 4; r++) {
        float v = tile[tx][ty + r * 8];
        __nv_bfloat16 h = __float2bfloat16(v);
        size_t o = (size_t)(n0 + ty + r * 8) * Cdim + k0 + tx;
        th[o] = h;
        tl[o] = __float2bfloat16(v - __bfloat162float(h));
    }
}

__global__ __launch_bounds__(256) void beff_kernel(
    const float* __restrict__ cab,
    const float* __restrict__ w0, const float* __restrict__ w1, const float* __restrict__ w2,
    const float* __restrict__ b0, const float* __restrict__ b1, const float* __restrict__ b2,
    float* __restrict__ beff)
{
    int i = blockIdx.x * 256 + threadIdx.x;
    int z = blockIdx.y;
    const float* W  = (z == 0) ? w0 : (z == 1) ? w1 : w2;
    const float* bb = (z == 0) ? b0 : (z == 1) ? b1 : b2;
    const float* c = cab + z * Cdim;
    float acc = bb[i];
    for (int k = 0; k < Cdim; k++) acc += c[k] * W[(size_t)k * Cdim + i];
    beff[z * Cdim + i] = acc;
}

// ====================== HMMA bf16x3 GEMM ===================================
// Tile M128 x N64, BK=64, 2-stage double buffer, 2 CTAs/SM.
// Stage: Ah 16K | Al 16K | Bh 8K | Bl 8K = 48 KB. Total smem 96 KB/CTA.
#define HG_STAGE 49152
#define HG_SMEM  (2 * HG_STAGE)

__device__ __forceinline__ void hg_load_stage(
    uint32_t sbase, int buf,
    const __nv_bfloat16* __restrict__ a_hi, const __nv_bfloat16* __restrict__ a_lo,
    size_t m0, int lda,
    const __nv_bfloat16* __restrict__ b_hi, const __nv_bfloat16* __restrict__ b_lo,
    size_t n0, int ldb, int k0, int tid)
{
    uint32_t sAh = sbase + buf * HG_STAGE;
    uint32_t sAl = sAh + 16384;
    uint32_t sBh = sAh + 32768;
    uint32_t sBl = sAh + 40960;
#pragma unroll
    for (int t = 0; t < 4; t++) {               // A: 128 rows x 64 k (hi+lo)
        int i = tid + t * 256;                  // 0..1023
        int row = i >> 3, u = i & 7;
        uint32_t soff = SWZ(row * 128 + u * 16);
        size_t ga = (m0 + row) * (size_t)lda + k0 + u * 8;
        cpa16(sAh + soff, a_hi + ga);
        cpa16(sAl + soff, a_lo + ga);
    }
#pragma unroll
    for (int t = 0; t < 2; t++) {               // B: 64 rows x 64 k (hi+lo)
        int i = tid + t * 256;                  // 0..511
        int row = i >> 3, u = i & 7;
        uint32_t soff = SWZ(row * 128 + u * 16);
        size_t gb = (n0 + row) * (size_t)ldb + k0 + u * 8;
        cpa16(sBh + soff, b_hi + gb);
        cpa16(sBl + soff, b_lo + gb);
    }
}

__global__ __launch_bounds__(256, 2) void hmma_gemm(
    const __nv_bfloat16* __restrict__ a_hi, const __nv_bfloat16* __restrict__ a_lo, int lda,
    const __nv_bfloat16* __restrict__ b_hi, const __nv_bfloat16* __restrict__ b_lo, int ldb,
    const float* __restrict__ bias,
    float* __restrict__ outf,
    __nv_bfloat16* __restrict__ out_hi, __nv_bfloat16* __restrict__ out_lo,
    int ldc, int K, float alpha, float alpha2, int mode,
    int az, int bz, int biasz, int cz)
{
    const int z = blockIdx.z;
    a_hi += (size_t)z * az;  a_lo += (size_t)z * az;
    b_hi += (size_t)z * bz;  b_lo += (size_t)z * bz;
    bias += (size_t)z * biasz;
    if (outf)  outf  += (size_t)z * cz;
    if (out_hi) { out_hi += (size_t)z * cz; out_lo += (size_t)z * cz; }
    const float alf = (z == 0) ? alpha : alpha2;

    extern __shared__ char sm[];
    const uint32_t sbase = smem_to_u32(sm);
    const int tid  = threadIdx.x;
    const int warp = tid >> 5, lane = tid & 31;
    const int wm0 = (warp >> 1) * 32;            // 0,32,64,96
    const int wn0 = (warp & 1) * 32;             // 0,32
    const size_t m0 = (size_t)blockIdx.y * 128;
    const size_t n0 = (size_t)blockIdx.x * 64;
    const int NC = K >> 6;

    float acc[2][4][4];
#pragma unroll
    for (int i = 0; i < 2; i++)
#pragma unroll
        for (int j = 0; j < 4; j++)
#pragma unroll
            for (int r = 0; r < 4; r++) acc[i][j][r] = 0.f;

    hg_load_stage(sbase, 0, a_hi, a_lo, m0, lda, b_hi, b_lo, n0, ldb, 0, tid);
    CPA_COMMIT();

    const int g = lane >> 3;
    const int l7 = lane & 7;

    for (int c = 0; c < NC; ++c) {
        CPA_WAIT0();
        __syncthreads();
        if (c + 1 < NC) {
            hg_load_stage(sbase, (c + 1) & 1, a_hi, a_lo, m0, lda,
                          b_hi, b_lo, n0, ldb, (c + 1) * 64, tid);
            CPA_COMMIT();
        }
        uint32_t sAh = sbase + (c & 1) * HG_STAGE;
        uint32_t sAl = sAh + 16384;
        uint32_t sBh = sAh + 32768;
        uint32_t sBl = sAh + 40960;

#pragma unroll
        for (int ks = 0; ks < 4; ks++) {
            uint32_t ah[2][4], al[2][4];
            {
                int arow = wm0 + (g & 1) * 8 + l7;
                int akb  = ks * 32 + ((g >> 1) & 1) * 16;
#pragma unroll
                for (int mt = 0; mt < 2; mt++) {
                    uint32_t off = SWZ((arow + mt * 16) * 128 + akb);
                    ldm_x4(ah[mt], sAh + off);
                    ldm_x4(al[mt], sAl + off);
                }
            }
            uint32_t bh[4][2], bl[4][2];
            {
                int nrow = wn0 + ((g >> 1) & 1) * 8 + l7;
                int bkb  = ks * 32 + (g & 1) * 16;
#pragma unroll
                for (int nt = 0; nt < 2; nt++) {
                    uint32_t off = SWZ((nrow + nt * 16) * 128 + bkb);
                    uint32_t r[4];
                    ldm_x4(r, sBh + off);
                    bh[nt * 2 + 0][0] = r[0]; bh[nt * 2 + 0][1] = r[1];
                    bh[nt * 2 + 1][0] = r[2]; bh[nt * 2 + 1][1] = r[3];
                    ldm_x4(r, sBl + off);
                    bl[nt * 2 + 0][0] = r[0]; bl[nt * 2 + 0][1] = r[1];
                    bl[nt * 2 + 1][0] = r[2]; bl[nt * 2 + 1][1] = r[3];
                }
            }
#pragma unroll
            for (int mt = 0; mt < 2; mt++)
#pragma unroll
                for (int j = 0; j < 4; j++)
                    mma16816(acc[mt][j], ah[mt], bh[j]);
#pragma unroll
            for (int mt = 0; mt < 2; mt++)
#pragma unroll
                for (int j = 0; j < 4; j++)
                    mma16816(acc[mt][j], ah[mt], bl[j]);
#pragma unroll
            for (int mt = 0; mt < 2; mt++)
#pragma unroll
                for (int j = 0; j < 4; j++)
                    mma16816(acc[mt][j], al[mt], bh[j]);
        }
    }

    const int qrow = lane >> 2;
    const int qcol = (lane & 3) * 2;
#pragma unroll
    for (int j = 0; j < 4; j++) {
        size_t col = n0 + wn0 + j * 8 + qcol;
        float b0 = bias[col], b1 = bias[col + 1];
#pragma unroll
        for (int mt = 0; mt < 2; mt++) {
            size_t row0 = m0 + wm0 + mt * 16 + qrow;
            size_t row1 = row0 + 8;
            float v00 = alf * (acc[mt][j][0] + b0);
            float v01 = alf * (acc[mt][j][1] + b1);
            float v10 = alf * (acc[mt][j][2] + b0);
            float v11 = alf * (acc[mt][j][3] + b1);
            if (mode == 0) {
                float2 r0 = {v00, v01}, r1 = {v10, v11};
                *(float2*)(outf + row0 * ldc + col) = r0;
                *(float2*)(outf + row1 * ldc + col) = r1;
            } else {
                __nv_bfloat162 hh0, ll0, hh1, ll1;
                hh0.x = __float2bfloat16(v00); hh0.y = __float2bfloat16(v01);
                ll0.x = __float2bfloat16(v00 - __bfloat162float(hh0.x));
                ll0.y = __float2bfloat16(v01 - __bfloat162float(hh0.y));
                hh1.x = __float2bfloat16(v10); hh1.y = __float2bfloat16(v11);
                ll1.x = __float2bfloat16(v10 - __bfloat162float(hh1.x));
                ll1.y = __float2bfloat16(v11 - __bfloat162float(hh1.y));
                *(uint32_t*)((char*)out_hi + (row0 * ldc + col) * 2) = *(uint32_t*)&hh0;
                *(uint32_t*)((char*)out_lo + (row0 * ldc + col) * 2) = *(uint32_t*)&ll0;
                *(uint32_t*)((char*)out_hi + (row1 * ldc + col) * 2) = *(uint32_t*)&hh1;
                *(uint32_t*)((char*)out_lo + (row1 * ldc + col) * 2) = *(uint32_t*)&ll1;
            }
        }
    }
}

// ================= HMMA dilated attention (all 3 branches, one launch) =====
#define FA_SMEM 98304

__global__ __launch_bounds__(256) void attn_hmma_all(
    const __nv_bfloat16* __restrict__ qh_g, const __nv_bfloat16* __restrict__ ql_g,
    const __nv_bfloat16* __restrict__ kh_g, const __nv_bfloat16* __restrict__ kl_g,
    const __nv_bfloat16* __restrict__ vh_g, const __nv_bfloat16* __restrict__ vl_g,
    float* __restrict__ O1, float* __restrict__ O2, float* __restrict__ O3,
    float* __restrict__ L1, float* __restrict__ L2, float* __restrict__ L3)
{
    extern __shared__ char sm[];
    const uint32_t sbase = smem_to_u32(sm);
    const uint32_t sQh = sbase, sQl = sbase + 16384;

    int bx = blockIdx.x;
    int W, R;
    float *Obuf, *Lbuf;
    if (bx < 32)      { W = 512;  R = 1; Obuf = O1; Lbuf = L1; }
    else if (bx < 48) { W = 1024; R = 2; Obuf = O2; Lbuf = L2; bx -= 32; }
    else              { W = 2048; R = 4; Obuf = O3; Lbuf = L3; bx -= 48; }
    const int seg = bx >> 2;
    const int qt  = bx & 3;

    const int b   = blockIdx.z;
    const int h   = blockIdx.y;
    const int tid = threadIdx.x;
    const int warp = tid >> 5, lane = tid & 31;
    const int g = lane >> 3, l7 = lane & 7;
    const int segbase = seg * W + (h & (R - 1));
    const int qBase = qt * 128;
    const size_t hoff = (size_t)h * Ddim;

#pragma unroll
    for (int t = 0; t < 4; t++) {
        int i = tid + t * 256;
        int row = i >> 3, u = i & 7;
        int tp = segbase + (qBase + row) * R;
        size_t gidx = (size_t)(b * Tdim + tp) * Cdim + hoff + u * 8;
        uint32_t off = SWZ(row * 128 + u * 16);
        cpa16(sQh + off, qh_g + gidx);
        cpa16(sQl + off, ql_g + gidx);
    }
    {
        uint32_t st = sbase + 32768;
#pragma unroll
        for (int t = 0; t < 2; t++) {
            int i = tid + t * 256;
            int row = i >> 3, u = i & 7;
            int tp = segbase + row * R;
            size_t gidx = (size_t)(b * Tdim + tp) * Cdim + hoff + u * 8;
            uint32_t off = SWZ(row * 128 + u * 16);
            cpa16(st +         off, kh_g + gidx);
            cpa16(st +  8192 + off, kl_g + gidx);
            cpa16(st + 16384 + off, vh_g + gidx);
            cpa16(st + 24576 + off, vl_g + gidx);
        }
    }
    CPA_COMMIT();

    uint32_t qfh[4][4], qfl[4][4];
    float oa[8][4];
#pragma unroll
    for (int nt = 0; nt < 8; nt++)
#pragma unroll
        for (int r = 0; r < 4; r++) oa[nt][r] = 0.f;
    float m0 = -1e30f, m1 = -1e30f, l0 = 0.f, l1 = 0.f;

    const int r0 = lane >> 2;
    const int row0 = qBase + warp * 16 + r0;
    const int row1 = row0 + 8;
    const int colb = (lane & 3) * 2;

    const int ntiles = qt * 2 + 2;
    for (int jt = 0; jt < ntiles; jt++) {
        const int j0 = jt * 64;
        CPA_WAIT0();
        __syncthreads();
        if (jt == 0) {
            int arow = warp * 16 + (g & 1) * 8 + l7;
#pragma unroll
            for (int ks = 0; ks < 4; ks++) {
                int akb = ks * 32 + ((g >> 1) & 1) * 16;
                uint32_t off = SWZ(arow * 128 + akb);
                ldm_x4(qfh[ks], sQh + off);
                ldm_x4(qfl[ks], sQl + off);
            }
        }
        if (jt + 1 < ntiles) {
            uint32_t st = sbase + 32768 + ((jt + 1) & 1) * 32768;
            int jn0 = (jt + 1) * 64;
#pragma unroll
            for (int t = 0; t < 2; t++) {
                int i = tid + t * 256;
                int row = i >> 3, u = i & 7;
                int tp = segbase + (jn0 + row) * R;
                size_t gidx = (size_t)(b * Tdim + tp) * Cdim + hoff + u * 8;
                uint32_t off = SWZ(row * 128 + u * 16);
                cpa16(st +         off, kh_g + gidx);
                cpa16(st +  8192 + off, kl_g + gidx);
                cpa16(st + 16384 + off, vh_g + gidx);
                cpa16(st + 24576 + off, vl_g + gidx);
            }
            CPA_COMMIT();
        }

        uint32_t sKh = sbase + 32768 + (jt & 1) * 32768;
        uint32_t sKl = sKh + 8192;
        uint32_t sVh = sKh + 16384;
        uint32_t sVl = sKh + 24576;

        float sa[8][4];
#pragma unroll
        for (int j = 0; j < 8; j++)
#pragma unroll
            for (int r = 0; r < 4; r++) sa[j][r] = 0.f;

#pragma unroll
        for (int ks = 0; ks < 4; ks++) {
            uint32_t kfh[8][2], kfl[8][2];
            int nrow = ((g >> 1) & 1) * 8 + l7;
            int bkb  = ks * 32 + (g & 1) * 16;
#pragma unroll
            for (int nt16 = 0; nt16 < 4; nt16++) {
                uint32_t off = SWZ((nrow + nt16 * 16) * 128 + bkb);
                uint32_t r[4];
                ldm_x4(r, sKh + off);
                kfh[nt16 * 2 + 0][0] = r[0]; kfh[nt16 * 2 + 0][1] = r[1];
                kfh[nt16 * 2 + 1][0] = r[2]; kfh[nt16 * 2 + 1][1] = r[3];
                ldm_x4(r, sKl + off);
                kfl[nt16 * 2 + 0][0] = r[0]; kfl[nt16 * 2 + 0][1] = r[1];
                kfl[nt16 * 2 + 1][0] = r[2]; kfl[nt16 * 2 + 1][1] = r[3];
            }
#pragma unroll
            for (int j = 0; j < 8; j++) mma16816(sa[j], qfh[ks], kfh[j]);
#pragma unroll
            for (int j = 0; j < 8; j++) mma16816(sa[j], qfh[ks], kfl[j]);
#pragma unroll
            for (int j = 0; j < 8; j++) mma16816(sa[j], qfl[ks], kfh[j]);
        }

        if (jt >= 2 * qt) {
#pragma unroll
            for (int j = 0; j < 8; j++) {
                int key = j0 + j * 8 + colb;
                if (key     > row0) sa[j][0] = -1e30f;
                if (key + 1 > row0) sa[j][1] = -1e30f;
                if (key     > row1) sa[j][2] = -1e30f;
                if (key + 1 > row1) sa[j][3] = -1e30f;
            }
        }

        float rm0 = sa[0][0], rm1 = sa[0][2];
#pragma unroll
        for (int j = 0; j < 8; j++) {
            rm0 = fmaxf(rm0, fmaxf(sa[j][0], sa[j][1]));
            rm1 = fmaxf(rm1, fmaxf(sa[j][2], sa[j][3]));
        }
        rm0 = fmaxf(rm0, __shfl_xor_sync(0xffffffffu, rm0, 1));
        rm0 = fmaxf(rm0, __shfl_xor_sync(0xffffffffu, rm0, 2));
        rm1 = fmaxf(rm1, __shfl_xor_sync(0xffffffffu, rm1, 1));
        rm1 = fmaxf(rm1, __shfl_xor_sync(0xffffffffu, rm1, 2));
        float mn0 = fmaxf(m0, rm0), mn1 = fmaxf(m1, rm1);
        float sc0 = ex2f(m0 - mn0), sc1 = ex2f(m1 - mn1);
        float rs0 = 0.f, rs1 = 0.f;
#pragma unroll
        for (int j = 0; j < 8; j++) {
            sa[j][0] = ex2f(sa[j][0] - mn0);
            sa[j][1] = ex2f(sa[j][1] - mn0);
            sa[j][2] = ex2f(sa[j][2] - mn1);
            sa[j][3] = ex2f(sa[j][3] - mn1);
            rs0 += sa[j][0] + sa[j][1];
            rs1 += sa[j][2] + sa[j][3];
        }
        rs0 += __shfl_xor_sync(0xffffffffu, rs0, 1);
        rs0 += __shfl_xor_sync(0xffffffffu, rs0, 2);
        rs1 += __shfl_xor_sync(0xffffffffu, rs1, 1);
        rs1 += __shfl_xor_sync(0xffffffffu, rs1, 2);
        l0 = l0 * sc0 + rs0; l1 = l1 * sc1 + rs1;
        m0 = mn0; m1 = mn1;
#pragma unroll
        for (int nt = 0; nt < 8; nt++) {
            oa[nt][0] *= sc0; oa[nt][1] *= sc0;
            oa[nt][2] *= sc1; oa[nt][3] *= sc1;
        }

#pragma unroll
        for (int kc = 0; kc < 4; kc++) {
            uint32_t ah[4], al[4];
#pragma unroll
            for (int half = 0; half < 2; half++) {
                const float* p0 = sa[kc * 2 + half];
                __nv_bfloat162 h01, h23, lo01, lo23;
                h01.x = __float2bfloat16(p0[0]); h01.y = __float2bfloat16(p0[1]);
                h23.x = __float2bfloat16(p0[2]); h23.y = __float2bfloat16(p0[3]);
                lo01.x = __float2bfloat16(p0[0] - __bfloat162float(h01.x));
                lo01.y = __float2bfloat16(p0[1] - __bfloat162float(h01.y));
                lo23.x = __float2bfloat16(p0[2] - __bfloat162float(h23.x));
                lo23.y = __float2bfloat16(p0[3] - __bfloat162float(h23.y));
                ah[half * 2 + 0] = *(uint32_t*)&h01;
                ah[half * 2 + 1] = *(uint32_t*)&h23;
                al[half * 2 + 0] = *(uint32_t*)&lo01;
                al[half * 2 + 1] = *(uint32_t*)&lo23;
            }

            uint32_t vfh[8][2], vfl[8][2];
            int vrow = kc * 16 + (g & 1) * 8 + l7;
            int nhalf = (g >> 1) & 1;
#pragma unroll
            for (int nt16 = 0; nt16 < 4; nt16++) {
                uint32_t off = SWZ(vrow * 128 + nt16 * 32 + nhalf * 16);
                uint32_t r[4];
                ldm_x4t(r, sVh + off);
                vfh[nt16 * 2 + 0][0] = r[0]; vfh[nt16 * 2 + 0][1] = r[1];
                vfh[nt16 * 2 + 1][0] = r[2]; vfh[nt16 * 2 + 1][1] = r[3];
                ldm_x4t(r, sVl + off);
                vfl[nt16 * 2 + 0][0] = r[0]; vfl[nt16 * 2 + 0][1] = r[1];
                vfl[nt16 * 2 + 1][0] = r[2]; vfl[nt16 * 2 + 1][1] = r[3];
            }
#pragma unroll
            for (int nt = 0; nt < 8; nt++) mma16816(oa[nt], ah, vfh[nt]);
#pragma unroll
            for (int nt = 0; nt < 8; nt++) mma16816(oa[nt], al, vfh[nt]);
#pragma unroll
            for (int nt = 0; nt < 8; nt++) mma16816(oa[nt], ah, vfl[nt]);
        }
        __syncthreads();
    }

    float inv0 = 1.f / l0, inv1 = 1.f / l1;
    int tp0 = segbase + row0 * R;
    int tp1 = segbase + row1 * R;
    size_t ob0 = (size_t)(b * Tdim + tp0) * Cdim + hoff;
    size_t ob1 = (size_t)(b * Tdim + tp1) * Cdim + hoff;
#pragma unroll
    for (int nt = 0; nt < 8; nt++) {
        int d = nt * 8 + colb;
        float2 w0 = {oa[nt][0] * inv0, oa[nt][1] * inv0};
        float2 w1 = {oa[nt][2] * inv1, oa[nt][3] * inv1};
        *(float2*)(Obuf + ob0 + d) = w0;
        *(float2*)(Obuf + ob1 + d) = w1;
    }
    if ((lane & 3) == 0) {
        Lbuf[(size_t)(b * Tdim + tp0) * Hdim + h] = m0 * LN2F + logf(l0);
        Lbuf[(size_t)(b * Tdim + tp1) * Hdim + h] = m1 * LN2F + logf(l1);
    }
}

// ---------------- combine branches -> y (bf16 hi/lo split out) -------------
__global__ __launch_bounds__(256) void combine_kernel(
    const float* __restrict__ O1, const float* __restrict__ O2,
    const float* __restrict__ O3, const float* __restrict__ L1,
    const float* __restrict__ L2, const float* __restrict__ L3,
    __nv_bfloat16* __restrict__ Yh, __nv_bfloat16* __restrict__ Yl)
{
    int idx = blockIdx.x * 256 + threadIdx.x;
    int c = idx & (Cdim - 1);
    int bt = idx >> 10;
    int t = bt & (Tdim - 1);
    int h = c >> 6;
    int li = bt * Hdim + h;

    float l1 = L1[li];
    bool p2 = (((t ^ h) & 1) == 0);
    bool p3 = (((t ^ h) & 3) == 0);
    float l2 = p2 ? L2[li] : -1e30f;
    float l3 = p3 ? L3[li] : -1e30f;
    float m = fmaxf(l1, fmaxf(l2, l3));
    float w1 = __expf(l1 - m);
    float w2 = p2 ? __expf(l2 - m) : 0.f;
    float w3 = p3 ? __expf(l3 - m) : 0.f;
    float num = w1 * O1[idx];
    if (p2) num += w2 * O2[idx];
    if (p3) num += w3 * O3[idx];
    float y = num / (w1 + w2 + w3);
    __nv_bfloat16 hh = __float2bfloat16(y);
    Yh[idx] = hh;
    Yl[idx] = __float2bfloat16(y - __bfloat162float(hh));
}

// ---------------- launcher --------------------------------------------------
extern "C" void kernel_launch(void* const* d_in, const int* in_sizes, int n_in,
                              void* d_out, int out_size)
{
    const float* x        = (const float*)d_in[0];
    const float* c_attn_w = (const float*)d_in[1];
    const float* c_attn_b = (const float*)d_in[2];
    const float* q_w      = (const float*)d_in[3];
    const float* q_b      = (const float*)d_in[4];
    const float* k_w      = (const float*)d_in[5];
    const float* k_b      = (const float*)d_in[6];
    const float* v_w      = (const float*)d_in[7];
    const float* v_b      = (const float*)d_in[8];
    const float* o_w      = (const float*)d_in[9];
    const float* o_b      = (const float*)d_in[10];
    float* out = (float*)d_out;

    __nv_bfloat16 *p_xhi, *p_xlo, *p_cwsh, *p_cwsl, *p_wTh, *p_wTl;
    __nv_bfloat16 *p_weffh, *p_weffl, *p_attnh, *p_attnl, *p_yh, *p_yl;
    float *p_beff, *p_zero, *p_o1, *p_o2, *p_o3, *p_l1, *p_l2, *p_l3;
    cudaGetSymbolAddress((void**)&p_xhi, g_xhi);
    cudaGetSymbolAddress((void**)&p_xlo, g_xlo);
    cudaGetSymbolAddress((void**)&p_cwsh, g_cwsh);
    cudaGetSymbolAddress((void**)&p_cwsl, g_cwsl);
    cudaGetSymbolAddress((void**)&p_wTh, g_wTh);
    cudaGetSymbolAddress((void**)&p_wTl, g_wTl);
    cudaGetSymbolAddress((void**)&p_weffh, g_weffh);
    cudaGetSymbolAddress((void**)&p_weffl, g_weffl);
    cudaGetSymbolAddress((void**)&p_beff, g_beff);
    cudaGetSymbolAddress((void**)&p_zero, g_zero);
    cudaGetSymbolAddress((void**)&p_attnh, g_attnh);
    cudaGetSymbolAddress((void**)&p_attnl, g_attnl);
    cudaGetSymbolAddress((void**)&p_yh, g_yh);
    cudaGetSymbolAddress((void**)&p_yl, g_yl);
    cudaGetSymbolAddress((void**)&p_o1, g_o1);
    cudaGetSymbolAddress((void**)&p_o2, g_o2);
    cudaGetSymbolAddress((void**)&p_o3, g_o3);
    cudaGetSymbolAddress((void**)&p_l1, g_l1);
    cudaGetSymbolAddress((void**)&p_l2, g_l2);
    cudaGetSymbolAddress((void**)&p_l3, g_l3);

    __nv_bfloat16* p_owh = p_wTh + 3 * (size_t)WPLANE;
    __nv_bfloat16* p_owl = p_wTl + 3 * (size_t)WPLANE;

    cudaFuncSetAttribute(attn_hmma_all, cudaFuncAttributeMaxDynamicSharedMemorySize, FA_SMEM);
    cudaFuncSetAttribute(hmma_gemm, cudaFuncAttributeMaxDynamicSharedMemorySize, HG_SMEM);

    // ---- conversions ----
    split2_kernel<<<(PLANE + 3 * WPLANE) / 1024, 256>>>(
        x, p_xhi, p_xlo, c_attn_w, p_cwsh, p_cwsl);
    transpose_split4<<<dim3(32, 32, 4), 256>>>(q_w, k_w, v_w, o_w, p_wTh, p_wTl);
    beff_kernel<<<dim3(Cdim / 256, 3), 256>>>(c_attn_b, q_w, k_w, v_w, q_b, k_b, v_b, p_beff);

    // ---- weight combine: W_eff^T[z] = wT[z] @ cw_slice[z]^T (batched z=3) --
    hmma_gemm<<<dim3(Cdim / 64, Cdim / 128, 3), 256, HG_SMEM>>>(
        p_wTh, p_wTl, Cdim, p_cwsh, p_cwsl, 3 * Cdim, p_zero,
        nullptr, p_weffh, p_weffl, Cdim, Cdim, 1.f, 1.f, 1,
        WPLANE, Cdim, 0, WPLANE);

    // ---- fused q/k/v projections: attn[z] = x @ W_eff[z]^T + b_eff[z] ------
    hmma_gemm<<<dim3(Cdim / 64, MROWS / 128, 3), 256, HG_SMEM>>>(
        p_xhi, p_xlo, Cdim, p_weffh, p_weffl, Cdim, p_beff,
        nullptr, p_attnh, p_attnl, Cdim, Cdim, 0.125f * LOG2E, 1.f, 1,
        0, WPLANE, Cdim, PLANE);

    __nv_bfloat16* p_qh = p_attnh + 0 * (size_t)PLANE; __nv_bfloat16* p_ql = p_attnl + 0 * (size_t)PLANE;
    __nv_bfloat16* p_kh = p_attnh + 1 * (size_t)PLANE; __nv_bfloat16* p_kl = p_attnl + 1 * (size_t)PLANE;
    __nv_bfloat16* p_vh = p_attnh + 2 * (size_t)PLANE; __nv_bfloat16* p_vl = p_attnl + 2 * (size_t)PLANE;

    // ---- all three dilated-attention branches in ONE launch ----
    attn_hmma_all<<<dim3(56, Hdim, Bdim), 256, FA_SMEM>>>(
        p_qh, p_ql, p_kh, p_kl, p_vh, p_vl,
        p_o1, p_o2, p_o3, p_l1, p_l2, p_l3);

    // ---- combine -> y (bf16 split) ----
    combine_kernel<<<PLANE / 256, 256>>>(
        p_o1, p_o2, p_o3, p_l1, p_l2, p_l3, p_yh, p_yl);

    // ---- out = y @ o_w + o_b (fp32) ----
    hmma_gemm<<<dim3(Cdim / 64, MROWS / 128, 1), 256, HG_SMEM>>>(
        p_yh, p_yl, Cdim, p_owh, p_owl, Cdim, o_b,
        out, nullptr, nullptr, Cdim, Cdim, 1.f, 1.f, 0,
        0, 0, 0, 0);
}